// round 15
// baseline (speedup 1.0000x reference)
#include <cuda_runtime.h>
#include <cstdint>
#include <cstddef>

#define BB 8
#define CC 64
#define NN 8192
#define MM 2048
#define KK 16
#define FPSM 1433
#define RANDM 615
#define FULLMASK 0xffffffffu

#define STHR 512
#define PT   (NN / STHR)   // 16 points per thread
#define PRS  (PT / 2)      // 8 packed pairs per thread

#define KNN_MPB 128                 // centers per knn block
#define KNN_SUB 4                   // threads per center
#define KNN_RANGE (NN / KNN_SUB)    // 2048 points per sub-scan

// ---------------- device scratch (static: no allocations allowed) ----------
__device__ int   g_idx[BB * MM];                 // selected center indices
__device__ int   g_knn[BB * MM * KK];            // knn indices
__device__ float g_xT[(size_t)BB * NN * CC];     // x transposed to [B,N,C]

// ---------------- Threefry-2x32 (exact JAX) --------------------------------
__device__ __forceinline__ uint32_t rotl32(uint32_t v, int d) {
    return (v << d) | (v >> (32 - d));
}

__device__ __forceinline__ void tf2x32(uint32_t k0, uint32_t k1,
                                       uint32_t x0, uint32_t x1,
                                       uint32_t& o0, uint32_t& o1) {
    uint32_t ks2 = k0 ^ k1 ^ 0x1BD11BDAu;
    x0 += k0; x1 += k1;
#define TF_R(r) { x0 += x1; x1 = rotl32(x1, r); x1 ^= x0; }
    TF_R(13) TF_R(15) TF_R(26) TF_R(6)
    x0 += k1; x1 += ks2 + 1u;
    TF_R(17) TF_R(29) TF_R(16) TF_R(24)
    x0 += ks2; x1 += k0 + 2u;
    TF_R(13) TF_R(15) TF_R(26) TF_R(6)
    x0 += k0; x1 += k1 + 3u;
    TF_R(17) TF_R(29) TF_R(16) TF_R(24)
    x0 += k1; x1 += ks2 + 4u;
    TF_R(13) TF_R(15) TF_R(26) TF_R(6)
    x0 += ks2; x1 += k0 + 5u;
#undef TF_R
    o0 = x0; o1 = x1;
}

__device__ __forceinline__ uint32_t rbits32(uint32_t ka, uint32_t kb, uint32_t i) {
    uint32_t a, b;
    tf2x32(ka, kb, 0u, i, a, b);
    return a ^ b;
}

// ---------------- f32x2 packed helpers (sm_103a) ----------------------------
__device__ __forceinline__ unsigned long long pk2(float lo, float hi) {
    unsigned long long r;
    asm("mov.b64 %0, {%1, %2};" : "=l"(r) : "f"(lo), "f"(hi));
    return r;
}
__device__ __forceinline__ void upk2(unsigned long long v, float& lo, float& hi) {
    asm("mov.b64 {%0, %1}, %2;" : "=f"(lo), "=f"(hi) : "l"(v));
}
__device__ __forceinline__ unsigned long long add2(unsigned long long a,
                                                   unsigned long long b) {
    unsigned long long r;
    asm("add.rn.f32x2 %0, %1, %2;" : "=l"(r) : "l"(a), "l"(b));
    return r;
}
__device__ __forceinline__ unsigned long long mul2(unsigned long long a,
                                                   unsigned long long b) {
    unsigned long long r;
    asm("mul.rn.f32x2 %0, %1, %2;" : "=l"(r) : "l"(a), "l"(b));
    return r;
}

// ---------------- kernel 1: transpose x [B,C,N] -> [B,N,C] -----------------
__global__ void transpose_kernel(const float* __restrict__ x) {
    __shared__ float t[32][33];
    int b  = blockIdx.z;
    int n0 = blockIdx.x * 32;
    int c0 = blockIdx.y * 32;
    int tx = threadIdx.x, ty = threadIdx.y;   // (32, 8)
#pragma unroll
    for (int r = 0; r < 32; r += 8)
        t[ty + r][tx] = x[((size_t)b * CC + c0 + ty + r) * NN + n0 + tx];
    __syncthreads();
#pragma unroll
    for (int r = 0; r < 32; r += 8)
        g_xT[((size_t)b * NN + n0 + ty + r) * CC + c0 + tx] = t[tx][ty + r];
}

// ---------------- kernel 2: FPS (blocks 0-7) + permutation (blocks 8-15) ---
__device__ __forceinline__ void bitonic8192(unsigned long long* s, int tid) {
    for (int k = 2; k <= 8192; k <<= 1) {
        for (int j = k >> 1; j > 0; j >>= 1) {
            __syncthreads();
            for (int t = tid; t < 8192; t += STHR) {
                int ixj = t ^ j;
                if (ixj > t) {
                    unsigned long long a = s[t], b = s[ixj];
                    bool up = ((t & k) == 0);
                    if ((a > b) == up) { s[t] = b; s[ixj] = a; }
                }
            }
        }
    }
    __syncthreads();
}

__global__ void __launch_bounds__(STHR, 1) sample_kernel(const float* __restrict__ pos) {
    extern __shared__ unsigned char s_raw[];
    __shared__ unsigned long long s_pair[2][16];   // (val<<32 | idx) per warp, by parity
    __shared__ float s_ctr[3];
    __shared__ uint32_t skey[2];
    int bid = blockIdx.x;
    int tid = threadIdx.x;
    int lane = tid & 31, wid = tid >> 5;

    if (bid < BB) {
        // ---------------- FPS for batch bid ----------------
        float* px = (float*)s_raw;
        float* py = px + NN;
        float* pz = py + NN;

        const float* pb = pos + (size_t)bid * 3 * NN;
        for (int i = tid; i < NN; i += STHR) {
            px[i] = pb[i];
            py[i] = pb[NN + i];
            pz[i] = pb[2 * NN + i];
        }
        __syncthreads();

        if (tid == 0) {
            uint32_t ka, kb; tf2x32(0u, 42u, 0u, (uint32_t)bid, ka, kb);
            uint32_t k2a, k2b; tf2x32(ka, kb, 0u, 1u, k2a, k2b);
            int start = (int)(rbits32(k2a, k2b, 0u) & (NN - 1));
            g_idx[bid * MM + 0] = start;
            s_ctr[0] = px[start]; s_ctr[1] = py[start]; s_ctr[2] = pz[start];
        }
        __syncthreads();

        // pack resident points: pair p covers indices tid+2p*512 (lo), tid+(2p+1)*512 (hi)
        unsigned long long qx[PRS], qy[PRS], qz[PRS];
        float dm[PT];
#pragma unroll
        for (int p = 0; p < PRS; p++) {
            int i0 = tid + (2 * p) * STHR, i1 = tid + (2 * p + 1) * STHR;
            qx[p] = pk2(px[i0], px[i1]);
            qy[p] = pk2(py[i0], py[i1]);
            qz[p] = pk2(pz[i0], pz[i1]);
            dm[2 * p] = 1e10f; dm[2 * p + 1] = 1e10f;
        }
        float cx = s_ctr[0], cy = s_ctr[1], cz = s_ctr[2];

        for (int s = 1; s < FPSM; s++) {
            int par = s & 1;
            // rn(q + (-c)) == rn(q - c) exactly
            unsigned long long ncx = pk2(-cx, -cx);
            unsigned long long ncy = pk2(-cy, -cy);
            unsigned long long ncz = pk2(-cz, -cz);
            float best = -1.0f; int bi = 0x7fffffff;
#pragma unroll
            for (int p = 0; p < PRS; p++) {
                unsigned long long dx = add2(qx[p], ncx);
                unsigned long long dy = add2(qy[p], ncy);
                unsigned long long dz = add2(qz[p], ncz);
                unsigned long long ss = add2(add2(mul2(dx, dx), mul2(dy, dy)),
                                             mul2(dz, dz));
                float d0, d1; upk2(ss, d0, d1);
                d0 = fminf(dm[2 * p], d0);     dm[2 * p] = d0;
                d1 = fminf(dm[2 * p + 1], d1); dm[2 * p + 1] = d1;
                // ascending index order preserves first-index tie-break
                if (d0 > best) { best = d0; bi = tid + (2 * p) * STHR; }
                if (d1 > best) { best = d1; bi = tid + (2 * p + 1) * STHR; }
            }
            // warp argmax: max on bits (d>=0 -> monotone), min index among ties
            uint32_t bb   = __float_as_uint(best);
            uint32_t wmax = __reduce_max_sync(FULLMASK, bb);
            uint32_t cand = (bb == wmax) ? (uint32_t)bi : 0xffffffffu;
            uint32_t widx = __reduce_min_sync(FULLMASK, cand);
            if (lane == 0)
                s_pair[par][wid] = ((unsigned long long)wmax << 32) | widx;
            __syncthreads();
            // every warp reduces the 16 warp-winners redundantly (no 2nd barrier)
            unsigned long long e = s_pair[par][lane & 15];
            uint32_t v   = (uint32_t)(e >> 32);
            uint32_t wi2 = (uint32_t)e;
            uint32_t m   = __reduce_max_sync(FULLMASK, v);
            uint32_t c2  = (v == m) ? wi2 : 0xffffffffu;
            uint32_t gi  = __reduce_min_sync(FULLMASK, c2);
            if (tid == 0) g_idx[bid * MM + s] = (int)gi;
            cx = px[gi]; cy = py[gi]; cz = pz[gi];
        }
    } else {
        // ---------------- permutation tail for batch bb ----------------
        int bb = bid - BB;
        unsigned long long* comp = (unsigned long long*)s_raw;   // [8192]
        uint32_t* val1 = (uint32_t*)(comp + NN);                 // [8192]

        if (tid == 0) {
            uint32_t ra, rb; tf2x32(0u, 42u, 0u, 1u, ra, rb);          // fold_in(root,1)
            uint32_t ka, kb; tf2x32(ra, rb, 0u, (uint32_t)bb, ka, kb); // rkeys[bb]
            skey[0] = ka; skey[1] = kb;
        }
        __syncthreads();

        for (int round = 0; round < 2; round++) {
            uint32_t ka = skey[0], kb = skey[1];
            uint32_t na, nb, sa, sb;
            tf2x32(ka, kb, 0u, 0u, na, nb);   // next key
            tf2x32(ka, kb, 0u, 1u, sa, sb);   // subkey
            for (int i = tid; i < NN; i += STHR) {
                uint32_t bits = rbits32(sa, sb, (uint32_t)i);
                comp[i] = ((unsigned long long)bits << 32) | (unsigned)i; // stable
            }
            __syncthreads();
            if (tid == 0) { skey[0] = na; skey[1] = nb; }
            bitonic8192(comp, tid);
            if (round == 0) {
                for (int i = tid; i < NN; i += STHR) val1[i] = (uint32_t)comp[i];
                __syncthreads();
            } else {
                for (int i = tid; i < RANDM; i += STHR)
                    g_idx[bb * MM + FPSM + i] = (int)val1[(uint32_t)comp[i]];
            }
        }
    }
}

// ---------------- kernel 3: split KNN (4 threads/center) + pos_sub ---------
// 128 blocks x 512 threads, 128 centers/block. Each sub scans a disjoint
// 2048-pt range keeping its stable local top-16; merge picks the 16
// lexicographically smallest (d2, idx) pairs = exact stable global top-16.
__global__ void __launch_bounds__(512, 1) knn_kernel(const float* __restrict__ pos,
                                                     float* __restrict__ out) {
    extern __shared__ unsigned char sm[];
    float4* pts = (float4*)sm;                                   // 131072 B
    float*  cd  = (float*)(pts + NN);                            // 128*64*4 B
    int*    ci  = (int*)(cd + KNN_MPB * 64);                     // 128*64*4 B

    int chunk = blockIdx.x >> 3;          // 0..15
    int b     = blockIdx.x & 7;
    int m0    = chunk * KNN_MPB;

    const float* pb = pos + (size_t)b * 3 * NN;
    for (int i = threadIdx.x; i < NN; i += 512) {
        float x = pb[i], y = pb[NN + i], z = pb[2 * NN + i];
        float sa = __fadd_rn(__fadd_rn(__fmul_rn(x, x), __fmul_rn(y, y)),
                             __fmul_rn(z, z));
        pts[i] = make_float4(x, y, z, sa);
    }
    __syncthreads();

    int g   = threadIdx.x >> 2;           // local center (0..127)
    int sub = threadIdx.x & 3;
    int m   = m0 + g;
    int cidx = g_idx[b * MM + m];
    float4 c = pts[cidx];
    float ss = c.w;

    float d16[KK]; int i16[KK];
#pragma unroll
    for (int s = 0; s < KK; s++) { d16[s] = 3.4e38f; i16[s] = 0; }
    float thresh = 3.4e38f;

    int n_begin = sub * KNN_RANGE, n_end = n_begin + KNN_RANGE;
#pragma unroll 4
    for (int n = n_begin; n < n_end; n++) {
        float4 p = pts[n];
        float dot = __fmul_rn(c.x, p.x);
        dot = __fmaf_rn(c.y, p.y, dot);
        dot = __fmaf_rn(c.z, p.z, dot);
        float d2 = __fsub_rn(__fadd_rn(ss, p.w), __fmul_rn(2.0f, dot));
        if (d2 < thresh) {
            float mv = -3.4e38f; int ms = 0;
#pragma unroll
            for (int s = 0; s < KK; s++) if (d16[s] > mv) { mv = d16[s]; ms = s; }
#pragma unroll
            for (int s = 0; s < KK; s++) if (s == ms) { d16[s] = d2; i16[s] = n; }
            mv = -3.4e38f;
#pragma unroll
            for (int s = 0; s < KK; s++) mv = fmaxf(mv, d16[s]);
            thresh = mv;
        }
    }
    // publish partial candidates
#pragma unroll
    for (int s = 0; s < KK; s++) {
        cd[g * 64 + sub * KK + s] = d16[s];
        ci[g * 64 + sub * KK + s] = i16[s];
    }
    __syncthreads();

    // merge: one thread per center selects 16 smallest (d2, idx) lexicographic
    if (threadIdx.x < KNN_MPB) {
        int g2 = threadIdx.x;
        int m2 = m0 + g2;
        float* md = cd + g2 * 64;
        int*   mi = ci + g2 * 64;
#pragma unroll 1
        for (int k = 0; k < KK; k++) {
            float bv = 3.4e38f; int bidx = 0x7fffffff; int bj = 0;
#pragma unroll 1
            for (int j = 0; j < 64; j++) {
                float v = md[j]; int ii = mi[j];
                if (v < bv || (v == bv && ii < bidx)) { bv = v; bidx = ii; bj = j; }
            }
            g_knn[((size_t)b * MM + m2) * KK + k] = bidx;
            md[bj] = 3.4e38f;
        }
        // pos_sub output
        float4 c2 = pts[g_idx[b * MM + m2]];
        float* psub = out + (size_t)BB * CC * MM;
        psub[((size_t)b * 3 + 0) * MM + m2] = c2.x;
        psub[((size_t)b * 3 + 1) * MM + m2] = c2.y;
        psub[((size_t)b * 3 + 2) * MM + m2] = c2.z;
    }
}

// ---------------- kernel 4: softmax weights + weighted gather-sum ----------
// SINGLE CHANGE vs R14: neighbor-row gather as float2 (LDG.64) — lane l owns
// channels {2l, 2l+1}. Per-channel arithmetic identical (rn mul + rn add,
// k ascending); only channel->lane mapping and tile store indices change.
__global__ void __launch_bounds__(256) out_kernel(const float* __restrict__ pos,
                                                  float* __restrict__ out) {
    __shared__ float tile[64 * 33];
    int bid  = blockIdx.x;              // 512 blocks = B * 64 tiles
    int b    = bid >> 6;
    int m0   = (bid & 63) * 32;
    int lane = threadIdx.x & 31, w = threadIdx.x >> 5;
    const float* pb = pos + (size_t)b * 3 * NN;
    const float* xb = g_xT + (size_t)b * NN * CC;

#pragma unroll 1
    for (int r = 0; r < 4; r++) {
        int cm = w * 4 + r;
        int m  = m0 + cm;
        int cidx = g_idx[b * MM + m];
        float cx = pb[cidx], cy = pb[NN + cidx], cz = pb[2 * NN + cidx];
        int nk = g_knn[((size_t)b * MM + m) * KK + (lane & 15)];
        float nx = pb[nk], ny = pb[NN + nk], nz = pb[2 * NN + nk];
        float dx = __fsub_rn(nx, cx), dy = __fsub_rn(ny, cy), dz = __fsub_rn(nz, cz);
        float d  = sqrtf(__fadd_rn(__fadd_rn(__fmul_rn(dx, dx), __fmul_rn(dy, dy)),
                                   __fmul_rn(dz, dz)));
        d = fmaxf(d, 1e-6f);
        float t = -__fdiv_rn(d, 0.2f);
        float tm = t;
#pragma unroll
        for (int o = 8; o > 0; o >>= 1) tm = fmaxf(tm, __shfl_xor_sync(FULLMASK, tm, o, 16));
        float e = expf(__fsub_rn(t, tm));
        float sum = 0.0f;
#pragma unroll
        for (int k = 0; k < KK; k++)
            sum = __fadd_rn(sum, __shfl_sync(FULLMASK, e, k, 16));
        float wgt = __fdiv_rn(e, sum);

        float a0 = 0.0f, a1 = 0.0f;
#pragma unroll
        for (int k = 0; k < KK; k++) {
            float wk = __shfl_sync(FULLMASK, wgt, k, 16);
            int   nn = __shfl_sync(FULLMASK, nk, k, 16);
            // one LDG.64 = channels {2*lane, 2*lane+1} of neighbor row
            float2 v = *(const float2*)(xb + (size_t)nn * CC + 2 * lane);
            a0 = __fadd_rn(a0, __fmul_rn(v.x, wk));
            a1 = __fadd_rn(a1, __fmul_rn(v.y, wk));
        }
        tile[(2 * lane)     * 33 + cm] = a0;
        tile[(2 * lane + 1) * 33 + cm] = a1;
    }
    __syncthreads();
    for (int e = threadIdx.x; e < 2048; e += 256) {
        int cch = e >> 5, mm = e & 31;
        out[((size_t)b * CC + cch) * MM + m0 + mm] = tile[cch * 33 + mm];
    }
}

// ---------------- launch ----------------------------------------------------
extern "C" void kernel_launch(void* const* d_in, const int* in_sizes, int n_in,
                              void* d_out, int out_size) {
    const float* x   = (const float*)d_in[0];
    const float* pos = (const float*)d_in[1];
    float* out = (float*)d_out;

    const int sample_smem = NN * 8 + NN * 4;                          // 98304
    const int knn_smem    = NN * (int)sizeof(float4) + KNN_MPB * 64 * 8; // 196608
    cudaFuncSetAttribute(sample_kernel, cudaFuncAttributeMaxDynamicSharedMemorySize, sample_smem);
    cudaFuncSetAttribute(knn_kernel,    cudaFuncAttributeMaxDynamicSharedMemorySize, knn_smem);

    transpose_kernel<<<dim3(NN / 32, CC / 32, BB), dim3(32, 8)>>>(x);
    sample_kernel<<<2 * BB, STHR, sample_smem>>>(pos);
    knn_kernel<<<128, 512, knn_smem>>>(pos, out);
    out_kernel<<<512, 256>>>(pos, out);
}

// round 16
// speedup vs baseline: 1.0283x; 1.0283x over previous
#include <cuda_runtime.h>
#include <cstdint>
#include <cstddef>

#define BB 8
#define CC 64
#define NN 8192
#define MM 2048
#define KK 16
#define FPSM 1433
#define RANDM 615
#define FULLMASK 0xffffffffu

#define STHR 256
#define NWARP (STHR / 32)  // 8 warps
#define PT   (NN / STHR)   // 32 points per thread
#define PRS  (PT / 2)      // 16 packed pairs per thread

#define KNN_MPB 128                 // centers per knn block
#define KNN_SUB 4                   // threads per center
#define KNN_RANGE (NN / KNN_SUB)    // 2048 points per sub-scan

// ---------------- device scratch (static: no allocations allowed) ----------
__device__ int   g_idx[BB * MM];                 // selected center indices
__device__ int   g_knn[BB * MM * KK];            // knn indices
__device__ float g_xT[(size_t)BB * NN * CC];     // x transposed to [B,N,C]

// ---------------- Threefry-2x32 (exact JAX) --------------------------------
__device__ __forceinline__ uint32_t rotl32(uint32_t v, int d) {
    return (v << d) | (v >> (32 - d));
}

__device__ __forceinline__ void tf2x32(uint32_t k0, uint32_t k1,
                                       uint32_t x0, uint32_t x1,
                                       uint32_t& o0, uint32_t& o1) {
    uint32_t ks2 = k0 ^ k1 ^ 0x1BD11BDAu;
    x0 += k0; x1 += k1;
#define TF_R(r) { x0 += x1; x1 = rotl32(x1, r); x1 ^= x0; }
    TF_R(13) TF_R(15) TF_R(26) TF_R(6)
    x0 += k1; x1 += ks2 + 1u;
    TF_R(17) TF_R(29) TF_R(16) TF_R(24)
    x0 += ks2; x1 += k0 + 2u;
    TF_R(13) TF_R(15) TF_R(26) TF_R(6)
    x0 += k0; x1 += k1 + 3u;
    TF_R(17) TF_R(29) TF_R(16) TF_R(24)
    x0 += k1; x1 += ks2 + 4u;
    TF_R(13) TF_R(15) TF_R(26) TF_R(6)
    x0 += ks2; x1 += k0 + 5u;
#undef TF_R
    o0 = x0; o1 = x1;
}

__device__ __forceinline__ uint32_t rbits32(uint32_t ka, uint32_t kb, uint32_t i) {
    uint32_t a, b;
    tf2x32(ka, kb, 0u, i, a, b);
    return a ^ b;
}

// ---------------- f32x2 packed helpers (sm_103a) ----------------------------
__device__ __forceinline__ unsigned long long pk2(float lo, float hi) {
    unsigned long long r;
    asm("mov.b64 %0, {%1, %2};" : "=l"(r) : "f"(lo), "f"(hi));
    return r;
}
__device__ __forceinline__ void upk2(unsigned long long v, float& lo, float& hi) {
    asm("mov.b64 {%0, %1}, %2;" : "=f"(lo), "=f"(hi) : "l"(v));
}
__device__ __forceinline__ unsigned long long add2(unsigned long long a,
                                                   unsigned long long b) {
    unsigned long long r;
    asm("add.rn.f32x2 %0, %1, %2;" : "=l"(r) : "l"(a), "l"(b));
    return r;
}
__device__ __forceinline__ unsigned long long mul2(unsigned long long a,
                                                   unsigned long long b) {
    unsigned long long r;
    asm("mul.rn.f32x2 %0, %1, %2;" : "=l"(r) : "l"(a), "l"(b));
    return r;
}

// ---------------- kernel 1: transpose x [B,C,N] -> [B,N,C] -----------------
__global__ void transpose_kernel(const float* __restrict__ x) {
    __shared__ float t[32][33];
    int b  = blockIdx.z;
    int n0 = blockIdx.x * 32;
    int c0 = blockIdx.y * 32;
    int tx = threadIdx.x, ty = threadIdx.y;   // (32, 8)
#pragma unroll
    for (int r = 0; r < 32; r += 8)
        t[ty + r][tx] = x[((size_t)b * CC + c0 + ty + r) * NN + n0 + tx];
    __syncthreads();
#pragma unroll
    for (int r = 0; r < 32; r += 8)
        g_xT[((size_t)b * NN + n0 + ty + r) * CC + c0 + tx] = t[tx][ty + r];
}

// ---------------- kernel 2: FPS (blocks 0-7) + permutation (blocks 8-15) ---
__device__ __forceinline__ void bitonic8192(unsigned long long* s, int tid) {
    for (int k = 2; k <= 8192; k <<= 1) {
        for (int j = k >> 1; j > 0; j >>= 1) {
            __syncthreads();
            for (int t = tid; t < 8192; t += STHR) {
                int ixj = t ^ j;
                if (ixj > t) {
                    unsigned long long a = s[t], b = s[ixj];
                    bool up = ((t & k) == 0);
                    if ((a > b) == up) { s[t] = b; s[ixj] = a; }
                }
            }
        }
    }
    __syncthreads();
}

__global__ void __launch_bounds__(STHR, 1) sample_kernel(const float* __restrict__ pos) {
    extern __shared__ unsigned char s_raw[];
    __shared__ unsigned long long s_pair[2][NWARP];  // (val<<32 | idx) per warp, by parity
    __shared__ float s_ctr[3];
    __shared__ uint32_t skey[2];
    int bid = blockIdx.x;
    int tid = threadIdx.x;
    int lane = tid & 31, wid = tid >> 5;

    if (bid < BB) {
        // ---------------- FPS for batch bid ----------------
        float* px = (float*)s_raw;
        float* py = px + NN;
        float* pz = py + NN;

        const float* pb = pos + (size_t)bid * 3 * NN;
        for (int i = tid; i < NN; i += STHR) {
            px[i] = pb[i];
            py[i] = pb[NN + i];
            pz[i] = pb[2 * NN + i];
        }
        __syncthreads();

        if (tid == 0) {
            uint32_t ka, kb; tf2x32(0u, 42u, 0u, (uint32_t)bid, ka, kb);
            uint32_t k2a, k2b; tf2x32(ka, kb, 0u, 1u, k2a, k2b);
            int start = (int)(rbits32(k2a, k2b, 0u) & (NN - 1));
            g_idx[bid * MM + 0] = start;
            s_ctr[0] = px[start]; s_ctr[1] = py[start]; s_ctr[2] = pz[start];
        }
        __syncthreads();

        // pack resident points: pair p covers indices tid+2p*256 (lo), tid+(2p+1)*256 (hi)
        unsigned long long qx[PRS], qy[PRS], qz[PRS];
        float dm[PT];
#pragma unroll
        for (int p = 0; p < PRS; p++) {
            int i0 = tid + (2 * p) * STHR, i1 = tid + (2 * p + 1) * STHR;
            qx[p] = pk2(px[i0], px[i1]);
            qy[p] = pk2(py[i0], py[i1]);
            qz[p] = pk2(pz[i0], pz[i1]);
            dm[2 * p] = 1e10f; dm[2 * p + 1] = 1e10f;
        }
        float cx = s_ctr[0], cy = s_ctr[1], cz = s_ctr[2];

        for (int s = 1; s < FPSM; s++) {
            int par = s & 1;
            // rn(q + (-c)) == rn(q - c) exactly
            unsigned long long ncx = pk2(-cx, -cx);
            unsigned long long ncy = pk2(-cy, -cy);
            unsigned long long ncz = pk2(-cz, -cz);
            float best = -1.0f; int bi = 0x7fffffff;
#pragma unroll
            for (int p = 0; p < PRS; p++) {
                unsigned long long dx = add2(qx[p], ncx);
                unsigned long long dy = add2(qy[p], ncy);
                unsigned long long dz = add2(qz[p], ncz);
                unsigned long long ss = add2(add2(mul2(dx, dx), mul2(dy, dy)),
                                             mul2(dz, dz));
                float d0, d1; upk2(ss, d0, d1);
                d0 = fminf(dm[2 * p], d0);     dm[2 * p] = d0;
                d1 = fminf(dm[2 * p + 1], d1); dm[2 * p + 1] = d1;
                // ascending index order preserves first-index tie-break
                if (d0 > best) { best = d0; bi = tid + (2 * p) * STHR; }
                if (d1 > best) { best = d1; bi = tid + (2 * p + 1) * STHR; }
            }
            // warp argmax: max on bits (d>=0 -> monotone), min index among ties
            uint32_t bb   = __float_as_uint(best);
            uint32_t wmax = __reduce_max_sync(FULLMASK, bb);
            uint32_t cand = (bb == wmax) ? (uint32_t)bi : 0xffffffffu;
            uint32_t widx = __reduce_min_sync(FULLMASK, cand);
            if (lane == 0)
                s_pair[par][wid] = ((unsigned long long)wmax << 32) | widx;
            __syncthreads();
            // every warp reduces the 8 warp-winners redundantly (no 2nd barrier)
            unsigned long long e = s_pair[par][lane & (NWARP - 1)];
            uint32_t v   = (uint32_t)(e >> 32);
            uint32_t wi2 = (uint32_t)e;
            uint32_t m   = __reduce_max_sync(FULLMASK, v);
            uint32_t c2  = (v == m) ? wi2 : 0xffffffffu;
            uint32_t gi  = __reduce_min_sync(FULLMASK, c2);
            if (tid == 0) g_idx[bid * MM + s] = (int)gi;
            cx = px[gi]; cy = py[gi]; cz = pz[gi];
        }
    } else {
        // ---------------- permutation tail for batch bb ----------------
        int bb = bid - BB;
        unsigned long long* comp = (unsigned long long*)s_raw;   // [8192]
        uint32_t* val1 = (uint32_t*)(comp + NN);                 // [8192]

        if (tid == 0) {
            uint32_t ra, rb; tf2x32(0u, 42u, 0u, 1u, ra, rb);          // fold_in(root,1)
            uint32_t ka, kb; tf2x32(ra, rb, 0u, (uint32_t)bb, ka, kb); // rkeys[bb]
            skey[0] = ka; skey[1] = kb;
        }
        __syncthreads();

        for (int round = 0; round < 2; round++) {
            uint32_t ka = skey[0], kb = skey[1];
            uint32_t na, nb, sa, sb;
            tf2x32(ka, kb, 0u, 0u, na, nb);   // next key
            tf2x32(ka, kb, 0u, 1u, sa, sb);   // subkey
            for (int i = tid; i < NN; i += STHR) {
                uint32_t bits = rbits32(sa, sb, (uint32_t)i);
                comp[i] = ((unsigned long long)bits << 32) | (unsigned)i; // stable
            }
            __syncthreads();
            if (tid == 0) { skey[0] = na; skey[1] = nb; }
            bitonic8192(comp, tid);
            if (round == 0) {
                for (int i = tid; i < NN; i += STHR) val1[i] = (uint32_t)comp[i];
                __syncthreads();
            } else {
                for (int i = tid; i < RANDM; i += STHR)
                    g_idx[bb * MM + FPSM + i] = (int)val1[(uint32_t)comp[i]];
            }
        }
    }
}

// ---------------- kernel 3: split KNN (4 threads/center) + pos_sub ---------
// 128 blocks x 512 threads, 128 centers/block. Each sub scans a disjoint
// 2048-pt range keeping its stable local top-16; merge picks the 16
// lexicographically smallest (d2, idx) pairs = exact stable global top-16.
__global__ void __launch_bounds__(512, 1) knn_kernel(const float* __restrict__ pos,
                                                     float* __restrict__ out) {
    extern __shared__ unsigned char sm[];
    float4* pts = (float4*)sm;                                   // 131072 B
    float*  cd  = (float*)(pts + NN);                            // 128*64*4 B
    int*    ci  = (int*)(cd + KNN_MPB * 64);                     // 128*64*4 B

    int chunk = blockIdx.x >> 3;          // 0..15
    int b     = blockIdx.x & 7;
    int m0    = chunk * KNN_MPB;

    const float* pb = pos + (size_t)b * 3 * NN;
    for (int i = threadIdx.x; i < NN; i += 512) {
        float x = pb[i], y = pb[NN + i], z = pb[2 * NN + i];
        float sa = __fadd_rn(__fadd_rn(__fmul_rn(x, x), __fmul_rn(y, y)),
                             __fmul_rn(z, z));
        pts[i] = make_float4(x, y, z, sa);
    }
    __syncthreads();

    int g   = threadIdx.x >> 2;           // local center (0..127)
    int sub = threadIdx.x & 3;
    int m   = m0 + g;
    int cidx = g_idx[b * MM + m];
    float4 c = pts[cidx];
    float ss = c.w;

    float d16[KK]; int i16[KK];
#pragma unroll
    for (int s = 0; s < KK; s++) { d16[s] = 3.4e38f; i16[s] = 0; }
    float thresh = 3.4e38f;

    int n_begin = sub * KNN_RANGE, n_end = n_begin + KNN_RANGE;
#pragma unroll 4
    for (int n = n_begin; n < n_end; n++) {
        float4 p = pts[n];
        float dot = __fmul_rn(c.x, p.x);
        dot = __fmaf_rn(c.y, p.y, dot);
        dot = __fmaf_rn(c.z, p.z, dot);
        float d2 = __fsub_rn(__fadd_rn(ss, p.w), __fmul_rn(2.0f, dot));
        if (d2 < thresh) {
            float mv = -3.4e38f; int ms = 0;
#pragma unroll
            for (int s = 0; s < KK; s++) if (d16[s] > mv) { mv = d16[s]; ms = s; }
#pragma unroll
            for (int s = 0; s < KK; s++) if (s == ms) { d16[s] = d2; i16[s] = n; }
            mv = -3.4e38f;
#pragma unroll
            for (int s = 0; s < KK; s++) mv = fmaxf(mv, d16[s]);
            thresh = mv;
        }
    }
    // publish partial candidates
#pragma unroll
    for (int s = 0; s < KK; s++) {
        cd[g * 64 + sub * KK + s] = d16[s];
        ci[g * 64 + sub * KK + s] = i16[s];
    }
    __syncthreads();

    // merge: one thread per center selects 16 smallest (d2, idx) lexicographic
    if (threadIdx.x < KNN_MPB) {
        int g2 = threadIdx.x;
        int m2 = m0 + g2;
        float* md = cd + g2 * 64;
        int*   mi = ci + g2 * 64;
#pragma unroll 1
        for (int k = 0; k < KK; k++) {
            float bv = 3.4e38f; int bidx = 0x7fffffff; int bj = 0;
#pragma unroll 1
            for (int j = 0; j < 64; j++) {
                float v = md[j]; int ii = mi[j];
                if (v < bv || (v == bv && ii < bidx)) { bv = v; bidx = ii; bj = j; }
            }
            g_knn[((size_t)b * MM + m2) * KK + k] = bidx;
            md[bj] = 3.4e38f;
        }
        // pos_sub output
        float4 c2 = pts[g_idx[b * MM + m2]];
        float* psub = out + (size_t)BB * CC * MM;
        psub[((size_t)b * 3 + 0) * MM + m2] = c2.x;
        psub[((size_t)b * 3 + 1) * MM + m2] = c2.y;
        psub[((size_t)b * 3 + 2) * MM + m2] = c2.z;
    }
}

// ---------------- kernel 4: softmax weights + weighted gather-sum ----------
__global__ void __launch_bounds__(256) out_kernel(const float* __restrict__ pos,
                                                  float* __restrict__ out) {
    __shared__ float tile[64 * 33];
    int bid  = blockIdx.x;              // 512 blocks = B * 64 tiles
    int b    = bid >> 6;
    int m0   = (bid & 63) * 32;
    int lane = threadIdx.x & 31, w = threadIdx.x >> 5;
    const float* pb = pos + (size_t)b * 3 * NN;
    const float* xb = g_xT + (size_t)b * NN * CC;

#pragma unroll 1
    for (int r = 0; r < 4; r++) {
        int cm = w * 4 + r;
        int m  = m0 + cm;
        int cidx = g_idx[b * MM + m];
        float cx = pb[cidx], cy = pb[NN + cidx], cz = pb[2 * NN + cidx];
        int nk = g_knn[((size_t)b * MM + m) * KK + (lane & 15)];
        float nx = pb[nk], ny = pb[NN + nk], nz = pb[2 * NN + nk];
        float dx = __fsub_rn(nx, cx), dy = __fsub_rn(ny, cy), dz = __fsub_rn(nz, cz);
        float d  = sqrtf(__fadd_rn(__fadd_rn(__fmul_rn(dx, dx), __fmul_rn(dy, dy)),
                                   __fmul_rn(dz, dz)));
        d = fmaxf(d, 1e-6f);
        float t = -__fdiv_rn(d, 0.2f);
        float tm = t;
#pragma unroll
        for (int o = 8; o > 0; o >>= 1) tm = fmaxf(tm, __shfl_xor_sync(FULLMASK, tm, o, 16));
        float e = expf(__fsub_rn(t, tm));
        float sum = 0.0f;
#pragma unroll
        for (int k = 0; k < KK; k++)
            sum = __fadd_rn(sum, __shfl_sync(FULLMASK, e, k, 16));
        float wgt = __fdiv_rn(e, sum);

        float a0 = 0.0f, a1 = 0.0f;
#pragma unroll
        for (int k = 0; k < KK; k++) {
            float wk = __shfl_sync(FULLMASK, wgt, k, 16);
            int   nn = __shfl_sync(FULLMASK, nk, k, 16);
            const float* row = xb + (size_t)nn * CC;
            a0 = __fadd_rn(a0, __fmul_rn(row[lane],      wk));
            a1 = __fadd_rn(a1, __fmul_rn(row[lane + 32], wk));
        }
        tile[lane * 33 + cm]        = a0;
        tile[(lane + 32) * 33 + cm] = a1;
    }
    __syncthreads();
    for (int e = threadIdx.x; e < 2048; e += 256) {
        int cch = e >> 5, mm = e & 31;
        out[((size_t)b * CC + cch) * MM + m0 + mm] = tile[cch * 33 + mm];
    }
}

// ---------------- launch ----------------------------------------------------
extern "C" void kernel_launch(void* const* d_in, const int* in_sizes, int n_in,
                              void* d_out, int out_size) {
    const float* x   = (const float*)d_in[0];
    const float* pos = (const float*)d_in[1];
    float* out = (float*)d_out;

    const int sample_smem = NN * 8 + NN * 4;                          // 98304
    const int knn_smem    = NN * (int)sizeof(float4) + KNN_MPB * 64 * 8; // 196608
    cudaFuncSetAttribute(sample_kernel, cudaFuncAttributeMaxDynamicSharedMemorySize, sample_smem);
    cudaFuncSetAttribute(knn_kernel,    cudaFuncAttributeMaxDynamicSharedMemorySize, knn_smem);

    transpose_kernel<<<dim3(NN / 32, CC / 32, BB), dim3(32, 8)>>>(x);
    sample_kernel<<<2 * BB, STHR, sample_smem>>>(pos);
    knn_kernel<<<128, 512, knn_smem>>>(pos, out);
    out_kernel<<<512, 256>>>(pos, out);
}